// round 17
// baseline (speedup 1.0000x reference)
#include <cuda_runtime.h>
#include <cstdint>

#define DIM       256
#define SLOTS     8
#define NMEM      1000000
#define NCTA      148
#define THREADS   288                 // 9 warps: 0-7 consumers, 8 producer
#define SROWS     64                  // rows per stage/tile (32 pairs)
#define PAIRB     2064                // 2 rows (2048B) + 16B pad  (516 words ≡ 4 mod 32)
#define STG_BYTES (32 * PAIRB)        // 66048
#define NSTG      3
#define KT_OFF    (NSTG * STG_BYTES)  // 198144 : kT[dim][slot] 8KB
#define WB_OFF    (KT_OFF + 8192)     // 206336 : per-warp w scratch 8 x 1KB
#define LB_OFF    (WB_OFF + 8192)     // 214528 : l partials 256B
#define BARS      (LB_OFF + 256)      // 214784
#define DYN_SMEM  (BARS + 64)         // 214848
#define SW_BYTES  (DIM * (DIM * (SLOTS + 1)) * 4)   // 2359296

typedef unsigned long long ull;

__device__ __align__(256) float g_k[SLOTS * DIM];          // heads*qspace*log2(e)
__device__ __align__(256) float g_qspace[SLOTS * DIM];
__device__ __align__(256) float g_pacc[NCTA * SLOTS * DIM];
__device__ __align__(256) float g_pl[NCTA * SLOTS];
__device__ __align__(256) float g_cat[DIM * (SLOTS + 1)];  // [state; newheads]
__device__ __align__(256) float g_newstate[DIM];

__device__ __forceinline__ ull ffma2(ull a, ull b, ull c) {
    ull d; asm("fma.rn.f32x2 %0, %1, %2, %3;" : "=l"(d) : "l"(a), "l"(b), "l"(c)); return d;
}
__device__ __forceinline__ float2 unpack2(ull v) {
    float2 f; asm("mov.b64 {%0, %1}, %2;" : "=f"(f.x), "=f"(f.y) : "l"(v)); return f;
}
__device__ __forceinline__ float ex2f(float x) {
    float r; asm("ex2.approx.f32 %0, %1;" : "=f"(r) : "f"(x)); return r;
}
__device__ __forceinline__ uint32_t smem_u32(const void* p) {
    uint32_t a; asm("{ .reg .u64 t; cvta.to.shared.u64 t, %1; cvt.u32.u64 %0, t; }" : "=r"(a) : "l"(p)); return a;
}
__device__ __forceinline__ void mbar_init(uint32_t a, uint32_t c) {
    asm volatile("mbarrier.init.shared.b64 [%0], %1;" :: "r"(a), "r"(c) : "memory");
}
__device__ __forceinline__ void mbar_arrive(uint32_t a) {
    asm volatile("mbarrier.arrive.release.cta.shared::cta.b64 _, [%0];" :: "r"(a) : "memory");
}
__device__ __forceinline__ void mbar_expect_tx(uint32_t a, uint32_t bytes) {
    asm volatile("mbarrier.arrive.expect_tx.shared.b64 _, [%0], %1;" :: "r"(a), "r"(bytes) : "memory");
}
__device__ __forceinline__ void mbar_wait(uint32_t a, uint32_t par) {
    asm volatile(
        "{\n\t.reg .pred P;\nWL%=:\n\t"
        "mbarrier.try_wait.parity.acquire.cta.shared::cta.b64 P, [%0], %1, 0x989680;\n\t"
        "@P bra.uni WD%=;\n\tbra.uni WL%=;\nWD%=:\n\t}" :: "r"(a), "r"(par) : "memory");
}
__device__ __forceinline__ void bulk_g2s(uint32_t dst, const void* src, uint32_t bytes, uint32_t mbar) {
    asm volatile("cp.async.bulk.shared::cta.global.mbarrier::complete_tx::bytes [%0], [%1], %2, [%3];"
                 :: "r"(dst), "l"(src), "r"(bytes), "r"(mbar) : "memory");
}
__device__ __forceinline__ void prefetchL2(const void* p) {
    asm volatile("prefetch.global.L2 [%0];" :: "l"(p));
}
// m16n8k8 tf32 HMMA, raw f32 bits as tf32
__device__ __forceinline__ void mma8(float& d0, float& d1, float& d2, float& d3,
                                     uint32_t a0, uint32_t a1, uint32_t a2, uint32_t a3,
                                     uint32_t b0, uint32_t b1) {
    asm volatile("mma.sync.aligned.m16n8k8.row.col.f32.tf32.tf32.f32 "
                 "{%0,%1,%2,%3}, {%4,%5,%6,%7}, {%8,%9}, {%0,%1,%2,%3};"
                 : "+f"(d0), "+f"(d1), "+f"(d2), "+f"(d3)
                 : "r"(a0), "r"(a1), "r"(a2), "r"(a3), "r"(b0), "r"(b1));
}

// ============================ Kernel 1: setup (warp-per-d, float4 loads) ============================
__global__ void __launch_bounds__(128) k_setup(const float* __restrict__ heads,
                                               const float* __restrict__ state,
                                               const float* __restrict__ qW,
                                               const float* __restrict__ qb)
{
    const int d = blockIdx.x * 4 + (threadIdx.x >> 5);   // 0..255
    const int lane = threadIdx.x & 31;
    float pc = 0.f, ps[SLOTS];
#pragma unroll
    for (int s = 0; s < SLOTS; s++) ps[s] = 0.f;
    const float4* w4 = (const float4*)(qW + (size_t)d * (2 * DIM));
    const float4* st4 = (const float4*)state;
    const float4* hd4 = (const float4*)heads;
#pragma unroll
    for (int it = 0; it < 2; it++) {              // state half: 64 float4
        int j4 = lane + it * 32;
        float4 w = w4[j4];
        float4 v = st4[j4];
        pc += w.x * v.x + w.y * v.y + w.z * v.z + w.w * v.w;
    }
#pragma unroll
    for (int it = 0; it < 2; it++) {              // heads half: 64 float4 per slot-dim
        int j4 = lane + it * 32;                  // float4 index within 256-dim
        float4 w = w4[64 + j4];
#pragma unroll
        for (int s = 0; s < SLOTS; s++) {
            float4 h = hd4[s * 64 + j4];
            ps[s] += w.x * h.x + w.y * h.y + w.z * h.z + w.w * h.w;
        }
    }
#pragma unroll
    for (int m = 16; m >= 1; m >>= 1) {
        pc += __shfl_xor_sync(0xffffffffu, pc, m);
#pragma unroll
        for (int s = 0; s < SLOTS; s++) ps[s] += __shfl_xor_sync(0xffffffffu, ps[s], m);
    }
    if (lane == 0) {
        float b = qb[d];
#pragma unroll
        for (int s = 0; s < SLOTS; s++) {
            float q = tanhf(ps[s] + pc + b);
            g_qspace[s * DIM + d] = q;
            g_k[s * DIM + d] = heads[s * DIM + d] * q * 1.4426950408889634f;
        }
    }
}

// ============================ Kernel 2: stream ============================
__global__ void __launch_bounds__(THREADS, 1) k_stream(const float* __restrict__ memory,
                                                       const float* __restrict__ sW)
{
    extern __shared__ char smem[];
    const int tid = threadIdx.x, lane = tid & 31, warp = tid >> 5;
    const int c = blockIdx.x;
    const int r0 = (int)(((long long)NMEM * c) / NCTA);
    const int r1 = (int)(((long long)NMEM * (c + 1)) / NCTA);
    const int T  = (r1 - r0 + SROWS - 1) / SROWS;

    const uint32_t sb = smem_u32(smem);
    const uint32_t FULL = sb + BARS, EMPTY = FULL + 24;

    if (tid == 0) {
#pragma unroll
        for (int i = 0; i < NSTG; i++) { mbar_init(FULL + 8 * i, 1); mbar_init(EMPTY + 8 * i, 4); }
    }
    // zero stages (tail rows finite on first use; later reuse masked via w=0)
    for (int i = tid; i < (NSTG * STG_BYTES) / 16; i += THREADS)
        *(float4*)(smem + i * 16) = make_float4(0.f, 0.f, 0.f, 0.f);
    // kT[dim][slot]
    {
        float* kT = (float*)(smem + KT_OFF);
        for (int i = tid; i < DIM * SLOTS; i += THREADS) {
            int dimi = i >> 3, s = i & 7;
            kT[dimi * 8 + s] = g_k[s * DIM + dimi];
        }
    }
    __syncthreads();

    // accumulators (consumers)
    ull acc2[SLOTS][4];
#pragma unroll
    for (int s = 0; s < SLOTS; s++) { acc2[s][0] = acc2[s][1] = acc2[s][2] = acc2[s][3] = 0ull; }
    float lp0 = 0.f, lp1 = 0.f;

    if (warp == 8) {
        // ------- producer: 32 x 2-row (2048B) bulk commands per tile, one per lane -------
        for (int t = 0; t < T; t++) {
            const int st = t % 3;
            if (t >= 3) mbar_wait(EMPTY + 8 * st, (t / 3 - 1) & 1);
            const int ts = r0 + t * SROWS;
            const int rows = (r1 - ts < SROWS) ? (r1 - ts) : SROWS;
            if (lane == 0) mbar_expect_tx(FULL + 8 * st, (uint32_t)rows * 1024u);
            __syncwarp();
            const int row0 = 2 * lane;
            if (row0 < rows) {
                const uint32_t bytes = (rows - row0 >= 2) ? 2048u : 1024u;
                bulk_g2s(sb + st * STG_BYTES + lane * PAIRB,
                         memory + (size_t)(ts + row0) * DIM, bytes, FULL + 8 * st);
            }
            if (t == T - 4) {
                // prefetch this CTA's slice of sW into L2 for k_synth (16KB = 128 lines)
                const char* pw = (const char*)sW + (size_t)c * 16384;
#pragma unroll
                for (int q = 0; q < 4; q++) {
                    size_t off = (size_t)(q * 32 + lane) * 128;
                    if ((size_t)c * 16384 + off < SW_BYTES) prefetchL2(pw + off);
                }
            }
        }
    } else {
        // ---------------- consumers: warps 0-3 even tiles, 4-7 odd tiles ----------------
        // Logical MMA rows 0-7 -> pair-row0 of the warp's 8 pairs; 8-15 -> pair-row1.
        const int g = warp >> 2, wgl = warp & 3;
        const int rowbase = wgl * 16;                 // 16 physical rows = pairs wgl*8 .. wgl*8+7
        const uint32_t* kTu = (const uint32_t*)(smem + KT_OFF);
        const uint32_t* bb = kTu + (lane & 3) * 8 + (lane >> 2);
        float* wb = (float*)(smem + WB_OFF + warp * 1024);

        // hoist tile-invariant B fragments into registers (64 regs)
        uint32_t breg0[32], breg1[32];
#pragma unroll
        for (int ks = 0; ks < 32; ks++) { breg0[ks] = bb[ks * 64]; breg1[ks] = bb[ks * 64 + 32]; }

        // A-fragment base: logical row lane>>2 -> pair (wgl*8 + (lane>>2)), row0
        const uint32_t aoff = (uint32_t)((wgl * 8 + (lane >> 2)) * PAIRB);

        for (int t = g; t < T; t += 2) {
            const int st = t % 3;
            mbar_wait(FULL + 8 * st, (t / 3) & 1);
            const int tstart = r0 + t * SROWS;
            const char* tile = smem + st * STG_BYTES;

            // ---- scores via tf32 HMMA: D[16 rows x 8 slots] (conflict-free A loads) ----
            float d0 = 0.f, d1 = 0.f, d2 = 0.f, d3 = 0.f;
            const uint32_t* af = (const uint32_t*)(tile + aoff) + (lane & 3);
#pragma unroll
            for (int ks = 0; ks < 32; ks++) {
                uint32_t a0 = af[ks * 8];
                uint32_t a1 = af[ks * 8 + 256];   // +1024B = pair row1
                uint32_t a2 = af[ks * 8 + 4];
                uint32_t a3 = af[ks * 8 + 260];
                mma8(d0, d1, d2, d3, a0, a1, a2, a3, breg0[ks], breg1[ks]);
            }
            // ---- exp + mask + stash dup pairs (physical rows: d0/d1 -> even, d2/d3 -> odd) ----
            const int pr0 = 2 * (lane >> 2);          // physical local row for d0/d1
            const int row0 = tstart + rowbase + pr0;
            const int row1 = row0 + 1;
            float w0 = (row0 < r1) ? ex2f(d0) : 0.f;
            float w1 = (row0 < r1) ? ex2f(d1) : 0.f;
            float w2 = (row1 < r1) ? ex2f(d2) : 0.f;
            float w3 = (row1 < r1) ? ex2f(d3) : 0.f;
            lp0 += w0 + w2;
            lp1 += w1 + w3;
            *(float4*)(wb + pr0 * 16 + (lane & 3) * 4)        = make_float4(w0, w0, w1, w1);
            *(float4*)(wb + (pr0 + 1) * 16 + (lane & 3) * 4)  = make_float4(w2, w2, w3, w3);
            __syncwarp();

            // ---- accumulate: acc2[s] += w[row][s] * x[row][dims of lane] ----
#pragma unroll 2
            for (int r = 0; r < 16; r++) {
                const char* xrow = tile + (wgl * 8 + (r >> 1)) * PAIRB + (r & 1) * 1024;
                ulonglong2 xA = *(const ulonglong2*)(xrow + 16 * lane);
                ulonglong2 xB = *(const ulonglong2*)(xrow + 512 + 16 * lane);
                const float4* wd4 = (const float4*)(wb + r * 16);
#pragma unroll
                for (int j = 0; j < 4; j++) {
                    float4 wp = wd4[j];
                    ull wa, wbp;
                    asm("mov.b64 %0, {%2, %3}; mov.b64 %1, {%4, %5};"
                        : "=l"(wa), "=l"(wbp) : "f"(wp.x), "f"(wp.y), "f"(wp.z), "f"(wp.w));
                    acc2[2 * j][0]     = ffma2(wa, xA.x, acc2[2 * j][0]);
                    acc2[2 * j][1]     = ffma2(wa, xA.y, acc2[2 * j][1]);
                    acc2[2 * j][2]     = ffma2(wa, xB.x, acc2[2 * j][2]);
                    acc2[2 * j][3]     = ffma2(wa, xB.y, acc2[2 * j][3]);
                    acc2[2 * j + 1][0] = ffma2(wbp, xA.x, acc2[2 * j + 1][0]);
                    acc2[2 * j + 1][1] = ffma2(wbp, xA.y, acc2[2 * j + 1][1]);
                    acc2[2 * j + 1][2] = ffma2(wbp, xB.x, acc2[2 * j + 1][2]);
                    acc2[2 * j + 1][3] = ffma2(wbp, xB.y, acc2[2 * j + 1][3]);
                }
            }
            __syncwarp();
            if (lane == 0) mbar_arrive(EMPTY + 8 * st);
        }
    }

    __syncthreads();   // pipeline fully drained — smem reusable
    if (warp < 8) {
        float* dst = (float*)(smem + warp * 8192);
#pragma unroll
        for (int s = 0; s < SLOTS; s++) {
            float2 u0 = unpack2(acc2[s][0]);
            float2 u1 = unpack2(acc2[s][1]);
            float2 u2 = unpack2(acc2[s][2]);
            float2 u3 = unpack2(acc2[s][3]);
            *(float4*)(dst + s * DIM + 4 * lane)       = make_float4(u0.x, u0.y, u1.x, u1.y);
            *(float4*)(dst + s * DIM + 128 + 4 * lane) = make_float4(u2.x, u2.y, u3.x, u3.y);
        }
#pragma unroll
        for (int m = 4; m < 32; m <<= 1) {
            lp0 += __shfl_xor_sync(0xffffffffu, lp0, m);
            lp1 += __shfl_xor_sync(0xffffffffu, lp1, m);
        }
        if (lane < 4) {
            float* lb = (float*)(smem + LB_OFF);
            lb[warp * 8 + 2 * lane]     = lp0;
            lb[warp * 8 + 2 * lane + 1] = lp1;
        }
    }
    __syncthreads();
    for (int e = tid; e < 2048; e += THREADS) {
        float sum = 0.f;
#pragma unroll
        for (int w = 0; w < 8; w++) sum += ((const float*)(smem + w * 8192))[e];
        g_pacc[c * 2048 + e] = sum;
    }
    if (tid < 8) {
        const float* lb = (const float*)(smem + LB_OFF);
        float sum = 0.f;
#pragma unroll
        for (int w = 0; w < 8; w++) sum += lb[w * 8 + tid];
        g_pl[c * 8 + tid] = sum;
    }
}

// ============================ Kernel 3: reduce (p-parallel) ============================
__global__ void k_reduce(const float* __restrict__ heads, const float* __restrict__ state)
{
    // grid 64 x 256: block handles 32 e-values, 8 p-groups
    const int ei = threadIdx.x & 31, pg = threadIdx.x >> 5;
    const int e = blockIdx.x * 32 + ei;
    const int s = e >> 8;
    float acc = 0.f, l = 0.f;
    for (int p = pg; p < NCTA; p += 8) {
        acc += g_pacc[p * 2048 + e];
        l   += g_pl[p * 8 + s];
    }
    __shared__ float sa[8][32], sl[8];
    sa[pg][ei] = acc;
    if (ei == 0) sl[pg] = l;
    __syncthreads();
    if (pg == 0) {
        float a = 0.f, lt = 0.f;
#pragma unroll
        for (int g = 0; g < 8; g++) { a += sa[g][ei]; lt += sl[g]; }
        float raw = a / lt;
        float q = g_qspace[e];
        g_cat[DIM + e] = raw * q + (1.f - q) * heads[e];
    }
    if (blockIdx.x == 0) {
        // copy state into g_cat[0:256] (256 threads)
        g_cat[threadIdx.x] = state[threadIdx.x];
    }
}

// ============================ Kernel 4: synth (warp-per-output, branchless) ============================
__global__ void __launch_bounds__(128) k_synth(const float* __restrict__ sW,
                                               const float* __restrict__ sb)
{
    const int i = blockIdx.x * 4 + (threadIdx.x >> 5);   // 0..255
    const int lane = threadIdx.x & 31;
    const float4* w4 = (const float4*)(sW + (size_t)i * (DIM * (SLOTS + 1)));
    const float4* cat4 = (const float4*)g_cat;
    float p0 = 0.f, p1 = 0.f, p2 = 0.f, p3 = 0.f;
#pragma unroll
    for (int it = 0; it < 18; it += 2) {
        int ja = lane + it * 32, jb = lane + (it + 1) * 32;
        float4 wa = w4[ja], ca = cat4[ja];
        float4 wc = w4[jb], cc = cat4[jb];
        p0 += wa.x * ca.x + wa.y * ca.y;
        p1 += wa.z * ca.z + wa.w * ca.w;
        p2 += wc.x * cc.x + wc.y * cc.y;
        p3 += wc.z * cc.z + wc.w * cc.w;
    }
    float p = (p0 + p1) + (p2 + p3);
#pragma unroll
    for (int m = 16; m >= 1; m >>= 1) p += __shfl_xor_sync(0xffffffffu, p, m);
    if (lane == 0) g_newstate[i] = p + sb[i];
}

// ============================ Kernel 5: out ============================
__global__ void k_out(const float* __restrict__ rvW, const float* __restrict__ rvb,
                      float* __restrict__ out)
{
    const int t = threadIdx.x;
    float ns = g_newstate[t];
    __shared__ float sm[256];
    sm[t] = ns * rvW[t];
    __syncthreads();
    for (int off = 128; off > 0; off >>= 1) { if (t < off) sm[t] += sm[t + off]; __syncthreads(); }
    __shared__ float rev;
    if (t == 0) rev = 1.f / (1.f + __expf(-(sm[0] + rvb[0])));
    __syncthreads();
    out[t] = ns * rev;
}

// ===================================================================================
extern "C" void kernel_launch(void* const* d_in, const int* in_sizes, int n_in,
                              void* d_out, int out_size)
{
    const float* memory = (const float*)d_in[0];
    const float* heads  = (const float*)d_in[1];
    const float* state  = (const float*)d_in[2];
    const float* qW     = (const float*)d_in[3];
    const float* qb     = (const float*)d_in[4];
    const float* sW     = (const float*)d_in[5];
    const float* sb     = (const float*)d_in[6];
    const float* rvW    = (const float*)d_in[7];
    const float* rvb    = (const float*)d_in[8];
    float* out = (float*)d_out;

    cudaFuncSetAttribute(k_stream, cudaFuncAttributeMaxDynamicSharedMemorySize, DYN_SMEM);

    k_setup<<<64, 128>>>(heads, state, qW, qb);
    k_stream<<<NCTA, THREADS, DYN_SMEM>>>(memory, sW);
    k_reduce<<<64, 256>>>(heads, state);
    k_synth<<<64, 128>>>(sW, sb);
    k_out<<<1, 256>>>(rvW, rvb, out);
}